// round 13
// baseline (speedup 1.0000x reference)
#include <cuda_runtime.h>
#include <math.h>
#include <stdint.h>

#define GN 8192
#define GF 512

// ---------------- device scratch (allocation-free) ----------------
__device__ __align__(16) float g_h  [GN * GF];  // h fp32 [j][f]
__device__ __align__(16) float g_htf[GF * GN];  // h^T tf32, FRAGMENT-PACKED
__device__ float g_s1[GN], g_s2[GN];
__device__ float g_E1[GN], g_F1[GN];
__device__ __align__(8) float2 g_EF2[GN];       // (E2, F2) packed

// ---------------------------------------------------------------------------
// Kernel 1: h = inp @ W1 + b1 (fp32 SGEMM 128x128x8)
// ---------------------------------------------------------------------------
__global__ __launch_bounds__(256) void gemm_h_kernel(
    const float* __restrict__ A,
    const float* __restrict__ B,
    const float* __restrict__ bias)
{
    __shared__ float As[8][132];
    __shared__ float Bs[8][128];

    const int tid = threadIdx.x;
    const int bx = blockIdx.x;
    const int by = blockIdx.y;
    const int tx = tid & 15;
    const int ty = tid >> 4;

    float acc[8][8];
#pragma unroll
    for (int i = 0; i < 8; i++)
#pragma unroll
        for (int j = 0; j < 8; j++) acc[i][j] = 0.f;

    const int a_r = tid >> 1;
    const int a_k = (tid & 1) * 4;
    const int b_k = tid >> 5;
    const int b_n = (tid & 31) * 4;

    const float* Aptr = A + (by * 128 + a_r) * GF + a_k;
    const float* Bptr = B + b_k * GF + bx * 128 + b_n;

    for (int k0 = 0; k0 < GF; k0 += 8) {
        float4 av = *(const float4*)(Aptr + k0);
        float4 bv = *(const float4*)(Bptr + k0 * GF);
        __syncthreads();
        As[a_k + 0][a_r] = av.x;
        As[a_k + 1][a_r] = av.y;
        As[a_k + 2][a_r] = av.z;
        As[a_k + 3][a_r] = av.w;
        *(float4*)&Bs[b_k][b_n] = bv;
        __syncthreads();

#pragma unroll
        for (int kk = 0; kk < 8; kk++) {
            float af[8], bf[8];
#pragma unroll
            for (int i = 0; i < 8; i++) af[i] = As[kk][ty * 8 + i];
#pragma unroll
            for (int j = 0; j < 8; j++) bf[j] = Bs[kk][tx * 8 + j];
#pragma unroll
            for (int i = 0; i < 8; i++)
#pragma unroll
                for (int j = 0; j < 8; j++) acc[i][j] += af[i] * bf[j];
        }
    }

    const int row0 = by * 128 + ty * 8;
    const int col0 = bx * 128 + tx * 8;
    float4 bb0 = *(const float4*)(bias + col0);
    float4 bb1 = *(const float4*)(bias + col0 + 4);
#pragma unroll
    for (int i = 0; i < 8; i++) {
        float4 v0, v1;
        v0.x = acc[i][0] + bb0.x; v0.y = acc[i][1] + bb0.y;
        v0.z = acc[i][2] + bb0.z; v0.w = acc[i][3] + bb0.w;
        v1.x = acc[i][4] + bb1.x; v1.y = acc[i][5] + bb1.y;
        v1.z = acc[i][6] + bb1.z; v1.w = acc[i][7] + bb1.w;
        *(float4*)&g_h[(row0 + i) * GF + col0]     = v0;
        *(float4*)&g_h[(row0 + i) * GF + col0 + 4] = v1;
    }
}

// ---------------------------------------------------------------------------
// Kernel 2: repack g_h -> g_htf (tf32-rounded, mma-fragment order).
// Block (w=0..7, t=0..255): f in [w*64,+64), j in [t*32,+32).
// float4 index: ((t*8+w)*2+kp)*256 + nt*32 + lane (lane = gid*4+tig)
// element: f = w*64+nt*8+gid, j = t*32+kp*16+slot*4+tig (slot = component)
// ---------------------------------------------------------------------------
__global__ __launch_bounds__(256) void repack_kernel()
{
    __shared__ float sm[32][68];
    const int tid = threadIdx.x;
    const int w = blockIdx.x;
    const int t = blockIdx.y;

#pragma unroll
    for (int rep = 0; rep < 2; rep++) {
        const int idx = tid + rep * 256;
        const int j = idx >> 4, fq = idx & 15;
        float4 v = *(const float4*)&g_h[(size_t)(t * 32 + j) * GF + w * 64 + fq * 4];
        unsigned u;
        asm("cvt.rna.tf32.f32 %0, %1;" : "=r"(u) : "f"(v.x)); v.x = __uint_as_float(u);
        asm("cvt.rna.tf32.f32 %0, %1;" : "=r"(u) : "f"(v.y)); v.y = __uint_as_float(u);
        asm("cvt.rna.tf32.f32 %0, %1;" : "=r"(u) : "f"(v.z)); v.z = __uint_as_float(u);
        asm("cvt.rna.tf32.f32 %0, %1;" : "=r"(u) : "f"(v.w)); v.w = __uint_as_float(u);
        *(float4*)&sm[j][fq * 4] = v;
    }
    __syncthreads();

    float4* dst = (float4*)g_htf + (size_t)(t * 8 + w) * 512;
#pragma unroll
    for (int rep = 0; rep < 2; rep++) {
        const int o = tid + rep * 256;
        const int kp = o >> 8, r = o & 255;
        const int nt = r >> 5, lane = r & 31;
        const int gid = lane >> 2, tig = lane & 3;
        const int fl = nt * 8 + gid;
        float4 v;
        v.x = sm[kp * 16 + 0 * 4 + tig][fl];
        v.y = sm[kp * 16 + 1 * 4 + tig][fl];
        v.z = sm[kp * 16 + 2 * 4 + tig][fl];
        v.w = sm[kp * 16 + 3 * 4 + tig][fl];
        dst[o] = v;
    }
}

// ---------------------------------------------------------------------------
// Kernel 3: s1/s2 dots
// ---------------------------------------------------------------------------
__global__ __launch_bounds__(128) void s1s2_kernel(
    const float* __restrict__ a1, const float* __restrict__ a2)
{
    const int row = blockIdx.x;
    const int tid = threadIdx.x;

    float4 hv = *(const float4*)(g_h + row * GF + tid * 4);
    float4 v1 = *(const float4*)(a1 + tid * 4);
    float4 v2 = *(const float4*)(a2 + tid * 4);
    float p1 = hv.x * v1.x + hv.y * v1.y + hv.z * v1.z + hv.w * v1.w;
    float p2 = hv.x * v2.x + hv.y * v2.y + hv.z * v2.z + hv.w * v2.w;

#pragma unroll
    for (int o = 16; o > 0; o >>= 1) {
        p1 += __shfl_down_sync(0xffffffffu, p1, o);
        p2 += __shfl_down_sync(0xffffffffu, p2, o);
    }
    __shared__ float r1[4], r2[4];
    const int lane = tid & 31, w = tid >> 5;
    if (lane == 0) { r1[w] = p1; r2[w] = p2; }
    __syncthreads();
    if (tid == 0) {
        g_s1[row] = r1[0] + r1[1] + r1[2] + r1[3];
        g_s2[row] = r2[0] + r2[1] + r2[2] + r2[3];
    }
}

// ---------------------------------------------------------------------------
// Kernel 4: factorized exp precompute. (E2,F2) packed as float2.
// ---------------------------------------------------------------------------
__global__ __launch_bounds__(256) void prep_kernel(const float* __restrict__ b2p)
{
    const int i = blockIdx.x * 256 + threadIdx.x;
    const float b2 = *b2p;
    const float x1 = g_s1[i] + b2;
    const float x2 = g_s2[i];
    g_E1[i] = __expf(x1);
    g_F1[i] = __expf(0.2f * x1);
    g_EF2[i] = make_float2(__expf(x2), __expf(0.2f * x2));
}

// ---------------------------------------------------------------------------
// Kernel 5: fused attention. AM=32 rows, FULL F=512, grid 256, 256 thr,
// 2 CTA/SM. AK=16 j-tiles (NTT=512): per warp per tile only 8 B-float4s ->
// IN-PLACE next-tile reload fits next to the 64-reg accumulator. PF (A frags)
// double-buffered float2, produced by all 256 threads -> ONE bar.sync/tile.
// ---------------------------------------------------------------------------
#define AM 32
#define AK 16
#define NTT (GN / AK)                    // 512

__device__ __forceinline__ void mma8u(float* c, float a0, float a1,
                                      float a2, float a3, float b0, float b1)
{
    asm volatile(
        "mma.sync.aligned.m16n8k8.row.col.f32.tf32.tf32.f32 "
        "{%0,%1,%2,%3}, {%4,%5,%6,%7}, {%8,%9}, {%0,%1,%2,%3};\n"
        : "+f"(c[0]), "+f"(c[1]), "+f"(c[2]), "+f"(c[3])
        : "r"(__float_as_uint(a0)), "r"(__float_as_uint(a1)),
          "r"(__float_as_uint(a2)), "r"(__float_as_uint(a3)),
          "r"(__float_as_uint(b0)), "r"(__float_as_uint(b1)));
}

__device__ __forceinline__ float tf32r(float x)
{
    unsigned u;
    asm("cvt.rna.tf32.f32 %0, %1;" : "=r"(u) : "f"(x));
    return __uint_as_float(u);
}

__global__ __launch_bounds__(256, 2) void gat_attn6(
    const int* __restrict__ adj, float* __restrict__ out)
{
    __shared__ float2 PF2[2][2][128];    // [buf][h][frag*32+lane], 4KB
    __shared__ float  ls[AM];

    const int tid  = threadIdx.x;
    const int w    = tid >> 5;           // warp 0..7 owns cols [w*64,+64)
    const int lane = tid & 31;
    const int gid  = lane >> 2;
    const int tig  = lane & 3;
    const int i0   = blockIdx.x * AM;

    if (tid < AM) ls[tid] = 0.f;

    // ---- producer identity: all 256 threads, one float2 each
    const int h     = tid >> 7;          // 0: (a0,a1) cols c; 1: (a2,a3) cols c+4
    const int q     = tid & 127;
    const int pfrag = q >> 5;            // = ks*2 + mt
    const int plane = q & 31;
    const int pgid  = plane >> 2;
    const int ptig  = plane & 3;
    const int pks   = pfrag >> 1;
    const int pmt   = pfrag & 1;
    const int r0 = pmt * 16 + pgid, r1 = r0 + 8;
    const int pc = pks * 8 + ptig + h * 4;   // col within [0,16)

    const float e1a = g_E1[i0 + r0], f1a = g_F1[i0 + r0];
    const float e1b = g_E1[i0 + r1], f1b = g_F1[i0 + r1];
    const int* arow0 = adj + (size_t)(i0 + r0) * GN;
    const int* arow1 = adj + (size_t)(i0 + r1) * GN;

    float lacc0 = 0.f, lacc1 = 0.f;
    float acc[2][8][4];
#pragma unroll
    for (int mt = 0; mt < 2; mt++)
#pragma unroll
        for (int nt = 0; nt < 8; nt++)
#pragma unroll
            for (int qq = 0; qq < 4; qq++) acc[mt][nt][qq] = 0.f;

    int aj0, aj1;
    float E2v, F2v;

#define PREF(T) do {                                                       \
    const int jj = (T) * AK + pc;                                          \
    aj0 = __ldg(arow0 + jj);                                               \
    aj1 = __ldg(arow1 + jj);                                               \
    float2 ef = __ldg(&g_EF2[jj]);                                         \
    E2v = ef.x; F2v = ef.y;                                                \
} while (0)

#define PRODUCE(PB) do {                                                   \
    float u0 = e1a * E2v, v0 = f1a * F2v;                                  \
    float u1 = e1b * E2v, v1 = f1b * F2v;                                  \
    float p0 = (aj0 > 0) ? (u0 > 1.f ? u0 : v0) : 0.f;                     \
    float p1 = (aj1 > 0) ? (u1 > 1.f ? u1 : v1) : 0.f;                     \
    p0 = tf32r(p0); p1 = tf32r(p1);                                        \
    lacc0 += p0; lacc1 += p1;                                              \
    PF2[PB][h][q] = make_float2(p0, p1);                                   \
} while (0)

    // ---- B mapping: float4 for (t, nt) at
    //      bbase + ((t>>1)*8 + w)*512 + (t&1)*256 + nt*32
    const float4* bbase = (const float4*)g_htf + lane;
#define BOFF(T) ((size_t)(((T) >> 1) * 8 + w) * 512 + ((T) & 1) * 256)

    float4 bq[8];
#pragma unroll
    for (int nt = 0; nt < 8; nt++)
        bq[nt] = __ldg(bbase + BOFF(0) + nt * 32);

    PREF(0);
    PRODUCE(0);
    PREF(1);
    __syncthreads();   // PF2[0] visible

    for (int t = 0; t < NTT; t++) {
        // ---- stage tile t+1's P fragments into the other buffer
        if (t + 1 < NTT) {
            PRODUCE((t + 1) & 1);
            if (t + 2 < NTT) PREF(t + 2);
        }

        // ---- A fragments for tile t
        const float2* pf0 = PF2[t & 1][0];
        const float2* pf1 = PF2[t & 1][1];
        const float2 A00 = pf0[0 * 32 + lane], A00h = pf1[0 * 32 + lane];
        const float2 A01 = pf0[1 * 32 + lane], A01h = pf1[1 * 32 + lane];
        const float2 A10 = pf0[2 * 32 + lane], A10h = pf1[2 * 32 + lane];
        const float2 A11 = pf0[3 * 32 + lane], A11h = pf1[3 * 32 + lane];

        // ---- MMAs + in-place B prefetch for tile t+1
        const int tn = (t + 1 < NTT) ? t + 1 : t;
        const size_t bo = BOFF(tn);
#pragma unroll
        for (int nt = 0; nt < 8; nt++) {
            const float4 bv = bq[nt];
            mma8u(acc[0][nt], A00.x, A00.y, A00h.x, A00h.y, bv.x, bv.y);
            mma8u(acc[1][nt], A01.x, A01.y, A01h.x, A01h.y, bv.x, bv.y);
            mma8u(acc[0][nt], A10.x, A10.y, A10h.x, A10h.y, bv.z, bv.w);
            mma8u(acc[1][nt], A11.x, A11.y, A11h.x, A11h.y, bv.z, bv.w);
            bq[nt] = __ldg(bbase + bo + nt * 32);   // distance ~ full tile
        }
        __syncthreads();   // PF2[t&1] consumed; PF2[(t+1)&1] complete
    }

    // ---- row sums (16 contributors per row)
    atomicAdd(&ls[r0], lacc0);
    atomicAdd(&ls[r1], lacc1);
    __syncthreads();

    // ---- epilogue: normalize + elu + store
#pragma unroll
    for (int mt = 0; mt < 2; mt++) {
        const int rA = mt * 16 + gid;
        const int rB = rA + 8;
        const float invA = 1.0f / ls[rA];
        const float invB = 1.0f / ls[rB];
#pragma unroll
        for (int nt = 0; nt < 8; nt++) {
            const int col = w * 64 + nt * 8 + tig * 2;
            float o0 = acc[0][nt][0] * 0.f, dummy;
            (void)o0; (void)dummy;
            float a0 = acc[mt][nt][0] * invA;
            float a1 = acc[mt][nt][1] * invA;
            float a2 = acc[mt][nt][2] * invB;
            float a3 = acc[mt][nt][3] * invB;
            a0 = a0 > 0.f ? a0 : (__expf(a0) - 1.f);
            a1 = a1 > 0.f ? a1 : (__expf(a1) - 1.f);
            a2 = a2 > 0.f ? a2 : (__expf(a2) - 1.f);
            a3 = a3 > 0.f ? a3 : (__expf(a3) - 1.f);
            *(float2*)&out[(size_t)(i0 + rA) * GF + col] = make_float2(a0, a1);
            *(float2*)&out[(size_t)(i0 + rB) * GF + col] = make_float2(a2, a3);
        }
    }
}

// ---------------------------------------------------------------------------
extern "C" void kernel_launch(void* const* d_in, const int* in_sizes, int n_in,
                              void* d_out, int out_size)
{
    const float* inp = (const float*)d_in[0];
    const int*   adj = (const int*)d_in[1];
    const float* W1  = (const float*)d_in[2];
    const float* b1  = (const float*)d_in[3];
    const float* a1  = (const float*)d_in[4];
    const float* a2  = (const float*)d_in[5];
    const float* b2  = (const float*)d_in[6];
    float* out = (float*)d_out;

    (void)in_sizes; (void)n_in; (void)out_size;

    gemm_h_kernel<<<dim3(GF / 128, GN / 128), 256>>>(inp, W1, b1);
    repack_kernel<<<dim3(8, 256), 256>>>();
    s1s2_kernel<<<GN, 128>>>(a1, a2);
    prep_kernel<<<GN / 256, 256>>>(b2);
    gat_attn6<<<GN / AM, 256>>>(adj, out);
}

// round 14
// speedup vs baseline: 1.2091x; 1.2091x over previous
#include <cuda_runtime.h>
#include <math.h>
#include <stdint.h>

#define GN 8192
#define GF 512

// ---------------- device scratch (allocation-free) ----------------
__device__ __align__(16) float g_h  [GN * GF];  // h fp32 [j][f]
__device__ __align__(16) float g_htf[GF * GN];  // h^T tf32, FRAGMENT-PACKED
__device__ float g_s1[GN], g_s2[GN];
__device__ float g_E1[GN], g_F1[GN], g_E2[GN], g_F2[GN];

// ---------------------------------------------------------------------------
// Kernel 1: h = inp @ W1 + b1 (fp32 SGEMM 128x128x8)
// ---------------------------------------------------------------------------
__global__ __launch_bounds__(256) void gemm_h_kernel(
    const float* __restrict__ A,
    const float* __restrict__ B,
    const float* __restrict__ bias)
{
    __shared__ float As[8][132];
    __shared__ float Bs[8][128];

    const int tid = threadIdx.x;
    const int bx = blockIdx.x;
    const int by = blockIdx.y;
    const int tx = tid & 15;
    const int ty = tid >> 4;

    float acc[8][8];
#pragma unroll
    for (int i = 0; i < 8; i++)
#pragma unroll
        for (int j = 0; j < 8; j++) acc[i][j] = 0.f;

    const int a_r = tid >> 1;
    const int a_k = (tid & 1) * 4;
    const int b_k = tid >> 5;
    const int b_n = (tid & 31) * 4;

    const float* Aptr = A + (by * 128 + a_r) * GF + a_k;
    const float* Bptr = B + b_k * GF + bx * 128 + b_n;

    for (int k0 = 0; k0 < GF; k0 += 8) {
        float4 av = *(const float4*)(Aptr + k0);
        float4 bv = *(const float4*)(Bptr + k0 * GF);
        __syncthreads();
        As[a_k + 0][a_r] = av.x;
        As[a_k + 1][a_r] = av.y;
        As[a_k + 2][a_r] = av.z;
        As[a_k + 3][a_r] = av.w;
        *(float4*)&Bs[b_k][b_n] = bv;
        __syncthreads();

#pragma unroll
        for (int kk = 0; kk < 8; kk++) {
            float af[8], bf[8];
#pragma unroll
            for (int i = 0; i < 8; i++) af[i] = As[kk][ty * 8 + i];
#pragma unroll
            for (int j = 0; j < 8; j++) bf[j] = Bs[kk][tx * 8 + j];
#pragma unroll
            for (int i = 0; i < 8; i++)
#pragma unroll
                for (int j = 0; j < 8; j++) acc[i][j] += af[i] * bf[j];
        }
    }

    const int row0 = by * 128 + ty * 8;
    const int col0 = bx * 128 + tx * 8;
    float4 bb0 = *(const float4*)(bias + col0);
    float4 bb1 = *(const float4*)(bias + col0 + 4);
#pragma unroll
    for (int i = 0; i < 8; i++) {
        float4 v0, v1;
        v0.x = acc[i][0] + bb0.x; v0.y = acc[i][1] + bb0.y;
        v0.z = acc[i][2] + bb0.z; v0.w = acc[i][3] + bb0.w;
        v1.x = acc[i][4] + bb1.x; v1.y = acc[i][5] + bb1.y;
        v1.z = acc[i][6] + bb1.z; v1.w = acc[i][7] + bb1.w;
        *(float4*)&g_h[(row0 + i) * GF + col0]     = v0;
        *(float4*)&g_h[(row0 + i) * GF + col0 + 4] = v1;
    }
}

// ---------------------------------------------------------------------------
// Kernel 2: repack g_h -> g_htf (tf32-rounded, mma-fragment order).
// Block (w=0..7, t=0..255): f in [w*64,+64), j in [t*32,+32).
// float4 index: ((t*8+w)*2+kp)*256 + nt*32 + lane (lane = gid*4+tig)
// element: f = w*64+nt*8+gid, j = t*32+kp*16+slot*4+tig (slot = component)
// ---------------------------------------------------------------------------
__global__ __launch_bounds__(256) void repack_kernel()
{
    __shared__ float sm[32][68];
    const int tid = threadIdx.x;
    const int w = blockIdx.x;
    const int t = blockIdx.y;

#pragma unroll
    for (int rep = 0; rep < 2; rep++) {
        const int idx = tid + rep * 256;
        const int j = idx >> 4, fq = idx & 15;
        float4 v = *(const float4*)&g_h[(size_t)(t * 32 + j) * GF + w * 64 + fq * 4];
        unsigned u;
        asm("cvt.rna.tf32.f32 %0, %1;" : "=r"(u) : "f"(v.x)); v.x = __uint_as_float(u);
        asm("cvt.rna.tf32.f32 %0, %1;" : "=r"(u) : "f"(v.y)); v.y = __uint_as_float(u);
        asm("cvt.rna.tf32.f32 %0, %1;" : "=r"(u) : "f"(v.z)); v.z = __uint_as_float(u);
        asm("cvt.rna.tf32.f32 %0, %1;" : "=r"(u) : "f"(v.w)); v.w = __uint_as_float(u);
        *(float4*)&sm[j][fq * 4] = v;
    }
    __syncthreads();

    float4* dst = (float4*)g_htf + (size_t)(t * 8 + w) * 512;
#pragma unroll
    for (int rep = 0; rep < 2; rep++) {
        const int o = tid + rep * 256;
        const int kp = o >> 8, r = o & 255;
        const int nt = r >> 5, lane = r & 31;
        const int gid = lane >> 2, tig = lane & 3;
        const int fl = nt * 8 + gid;
        float4 v;
        v.x = sm[kp * 16 + 0 * 4 + tig][fl];
        v.y = sm[kp * 16 + 1 * 4 + tig][fl];
        v.z = sm[kp * 16 + 2 * 4 + tig][fl];
        v.w = sm[kp * 16 + 3 * 4 + tig][fl];
        dst[o] = v;
    }
}

// ---------------------------------------------------------------------------
// Kernel 3: s1/s2 dots
// ---------------------------------------------------------------------------
__global__ __launch_bounds__(128) void s1s2_kernel(
    const float* __restrict__ a1, const float* __restrict__ a2)
{
    const int row = blockIdx.x;
    const int tid = threadIdx.x;

    float4 hv = *(const float4*)(g_h + row * GF + tid * 4);
    float4 v1 = *(const float4*)(a1 + tid * 4);
    float4 v2 = *(const float4*)(a2 + tid * 4);
    float p1 = hv.x * v1.x + hv.y * v1.y + hv.z * v1.z + hv.w * v1.w;
    float p2 = hv.x * v2.x + hv.y * v2.y + hv.z * v2.z + hv.w * v2.w;

#pragma unroll
    for (int o = 16; o > 0; o >>= 1) {
        p1 += __shfl_down_sync(0xffffffffu, p1, o);
        p2 += __shfl_down_sync(0xffffffffu, p2, o);
    }
    __shared__ float r1[4], r2[4];
    const int lane = tid & 31, w = tid >> 5;
    if (lane == 0) { r1[w] = p1; r2[w] = p2; }
    __syncthreads();
    if (tid == 0) {
        g_s1[row] = r1[0] + r1[1] + r1[2] + r1[3];
        g_s2[row] = r2[0] + r2[1] + r2[2] + r2[3];
    }
}

// ---------------------------------------------------------------------------
// Kernel 4: factorized exp precompute
// ---------------------------------------------------------------------------
__global__ __launch_bounds__(256) void prep_kernel(const float* __restrict__ b2p)
{
    const int i = blockIdx.x * 256 + threadIdx.x;
    const float b2 = *b2p;
    const float x1 = g_s1[i] + b2;
    const float x2 = g_s2[i];
    g_E1[i] = __expf(x1);
    g_F1[i] = __expf(0.2f * x1);
    g_E2[i] = __expf(x2);
    g_F2[i] = __expf(0.2f * x2);
}

// ---------------------------------------------------------------------------
// Kernel 5: fused attention (R11 winner + one-phase-ahead B rotation).
// AM=32, AK=32, full F, 256 threads, 2 CTA/SM. B: direct LDG from
// fragment-packed g_htf; the 8 bq regs of phase (t,kp) are reloaded inside
// the PREVIOUS phase's MMA loop (zero extra registers, distance >= 1 phase).
// ---------------------------------------------------------------------------
#define AM 32
#define AK 32
#define NTT (GN / AK)                    // 256

__device__ __forceinline__ void mma8(float* c, float4 a, float b0, float b1)
{
    asm volatile(
        "mma.sync.aligned.m16n8k8.row.col.f32.tf32.tf32.f32 "
        "{%0,%1,%2,%3}, {%4,%5,%6,%7}, {%8,%9}, {%0,%1,%2,%3};\n"
        : "+f"(c[0]), "+f"(c[1]), "+f"(c[2]), "+f"(c[3])
        : "r"(__float_as_uint(a.x)), "r"(__float_as_uint(a.y)),
          "r"(__float_as_uint(a.z)), "r"(__float_as_uint(a.w)),
          "r"(__float_as_uint(b0)), "r"(__float_as_uint(b1)));
}

__device__ __forceinline__ float tf32r(float x)
{
    unsigned u;
    asm("cvt.rna.tf32.f32 %0, %1;" : "=r"(u) : "f"(x));
    return __uint_as_float(u);
}

__global__ __launch_bounds__(256, 2) void gat_attn4(
    const int* __restrict__ adj, float* __restrict__ out)
{
    __shared__ float4 PF[256];           // 8 A-frags x 32 lanes
    __shared__ float  ls[AM];

    const int tid  = threadIdx.x;
    const int w    = tid >> 5;           // warp 0..7 == producer frag id
    const int lane = tid & 31;
    const int gid  = lane >> 2;
    const int tig  = lane & 3;
    const int i0   = blockIdx.x * AM;

    if (tid < AM) ls[tid] = 0.f;

    // producer identity: frag f = w = ks*2+mt
    const int pks = w >> 1;
    const int pmt = w & 1;
    const int r0 = pmt * 16 + gid, r1 = r0 + 8;
    const int c0 = pks * 8 + tig,  c1 = c0 + 4;

    const float e1a = g_E1[i0 + r0], f1a = g_F1[i0 + r0];
    const float e1b = g_E1[i0 + r1], f1b = g_F1[i0 + r1];
    const int* arow0 = adj + (size_t)(i0 + r0) * GN;
    const int* arow1 = adj + (size_t)(i0 + r1) * GN;

    float lacc0 = 0.f, lacc1 = 0.f;
    float acc[2][8][4];
#pragma unroll
    for (int mt = 0; mt < 2; mt++)
#pragma unroll
        for (int nt = 0; nt < 8; nt++)
#pragma unroll
            for (int q = 0; q < 4; q++) acc[mt][nt][q] = 0.f;

    int a00, a01, a10, a11;
    float E2a, E2b, F2a, F2b;

#define PREF(J) do {                                                       \
    a00 = __ldg(arow0 + (J) + c0); a01 = __ldg(arow0 + (J) + c1);          \
    a10 = __ldg(arow1 + (J) + c0); a11 = __ldg(arow1 + (J) + c1);          \
    E2a = __ldg(&g_E2[(J) + c0]);  E2b = __ldg(&g_E2[(J) + c1]);           \
    F2a = __ldg(&g_F2[(J) + c0]);  F2b = __ldg(&g_F2[(J) + c1]);           \
} while (0)

    PREF(0);

    // B base: warp w reads float4 idx ((t*8+w)*2+kp)*256 + nt*32 + lane
    const float4* bwarp = (const float4*)g_htf + (size_t)w * 512 + lane;

    // ---- prologue: bq holds B(t=0, kp=0)
    float4 bq[8];
#pragma unroll
    for (int nt = 0; nt < 8; nt++)
        bq[nt] = __ldg(bwarp + nt * 32);

    for (int t = 0; t < NTT; t++) {
        // ---- produce P fragments (factorized exp, zero MUFU)
        {
            float u00 = e1a * E2a, v00 = f1a * F2a;
            float u01 = e1a * E2b, v01 = f1a * F2b;
            float u10 = e1b * E2a, v10 = f1b * F2a;
            float u11 = e1b * E2b, v11 = f1b * F2b;
            float p00 = (a00 > 0) ? (u00 > 1.f ? u00 : v00) : 0.f;
            float p01 = (a01 > 0) ? (u01 > 1.f ? u01 : v01) : 0.f;
            float p10 = (a10 > 0) ? (u10 > 1.f ? u10 : v10) : 0.f;
            float p11 = (a11 > 0) ? (u11 > 1.f ? u11 : v11) : 0.f;
            p00 = tf32r(p00); p01 = tf32r(p01);
            p10 = tf32r(p10); p11 = tf32r(p11);
            lacc0 += p00 + p01; lacc1 += p10 + p11;
            PF[tid] = make_float4(p00, p10, p01, p11);
        }
        __syncthreads();                     // PF ready

        if (t + 1 < NTT) PREF((t + 1) * AK); // hide adj/EF latency under MMA

#pragma unroll
        for (int kp = 0; kp < 2; kp++) {
            // B address of the NEXT phase: (t,1) after kp0; (t+1,0) after kp1
            const int tnx  = (kp == 0) ? t : (t + 1 < NTT ? t + 1 : 0);
            const int kpnx = (kp == 0) ? 1 : 0;
            const float4* bnx = bwarp + (size_t)((tnx * 8) * 2 + kpnx) * 256;

            // A frags for ks = 2kp, 2kp+1 (frag f = ks*2+mt)
            const float4 afA0 = PF[(4 * kp + 0) * 32 + lane];
            const float4 afA1 = PF[(4 * kp + 1) * 32 + lane];
            const float4 afB0 = PF[(4 * kp + 2) * 32 + lane];
            const float4 afB1 = PF[(4 * kp + 3) * 32 + lane];

#pragma unroll
            for (int nt = 0; nt < 8; nt++) {
                const float4 bv = bq[nt];
                mma8(acc[0][nt], afA0, bv.x, bv.y);
                mma8(acc[1][nt], afA1, bv.x, bv.y);
                mma8(acc[0][nt], afB0, bv.z, bv.w);
                mma8(acc[1][nt], afB1, bv.z, bv.w);
                bq[nt] = __ldg(bnx + nt * 32);   // prefetch next phase's B
            }
        }
        __syncthreads();                     // PF consumed (WAR for t+1)
    }

    // ---- row sums: 16 threads contribute per row
    atomicAdd(&ls[r0], lacc0);
    atomicAdd(&ls[r1], lacc1);
    __syncthreads();

    // ---- epilogue: normalize + elu + store
#pragma unroll
    for (int mt = 0; mt < 2; mt++) {
        const int rA = mt * 16 + gid;
        const int rB = rA + 8;
        const float invA = 1.0f / ls[rA];
        const float invB = 1.0f / ls[rB];
#pragma unroll
        for (int nt = 0; nt < 8; nt++) {
            const int col = w * 64 + nt * 8 + tig * 2;
            float o0 = acc[mt][nt][0] * invA;
            float o1 = acc[mt][nt][1] * invA;
            float o2 = acc[mt][nt][2] * invB;
            float o3 = acc[mt][nt][3] * invB;
            o0 = o0 > 0.f ? o0 : (__expf(o0) - 1.f);
            o1 = o1 > 0.f ? o1 : (__expf(o1) - 1.f);
            o2 = o2 > 0.f ? o2 : (__expf(o2) - 1.f);
            o3 = o3 > 0.f ? o3 : (__expf(o3) - 1.f);
            *(float2*)&out[(size_t)(i0 + rA) * GF + col] = make_float2(o0, o1);
            *(float2*)&out[(size_t)(i0 + rB) * GF + col] = make_float2(o2, o3);
        }
    }
}

// ---------------------------------------------------------------------------
extern "C" void kernel_launch(void* const* d_in, const int* in_sizes, int n_in,
                              void* d_out, int out_size)
{
    const float* inp = (const float*)d_in[0];
    const int*   adj = (const int*)d_in[1];
    const float* W1  = (const float*)d_in[2];
    const float* b1  = (const float*)d_in[3];
    const float* a1  = (const float*)d_in[4];
    const float* a2  = (const float*)d_in[5];
    const float* b2  = (const float*)d_in[6];
    float* out = (float*)d_out;

    (void)in_sizes; (void)n_in; (void)out_size;

    gemm_h_kernel<<<dim3(GF / 128, GN / 128), 256>>>(inp, W1, b1);
    repack_kernel<<<dim3(8, 256), 256>>>();
    s1s2_kernel<<<GN, 128>>>(a1, a2);
    prep_kernel<<<GN / 256, 256>>>(b2);
    gat_attn4<<<GN / AM, 256>>>(adj, out);
}

// round 16
// speedup vs baseline: 1.4062x; 1.1631x over previous
#include <cuda_runtime.h>
#include <math.h>
#include <stdint.h>

#define GN 8192
#define GF 512

// ---------------- device scratch (allocation-free) ----------------
__device__ __align__(16) float g_htf[GF * GN];  // h^T tf32, FRAGMENT-PACKED
__device__ float g_s1p[4][GN], g_s2p[4][GN];    // per-f-quarter partial dots
__device__ float g_E1[GN], g_F1[GN], g_E2[GN], g_F2[GN];

// ---------------------------------------------------------------------------
// Kernel 1: h = inp @ W1 + b1 (fp32 SGEMM 128x128x8) with FUSED epilogue:
//   (a) s1/s2 partial dots (h·a1, h·a2) -> g_s1p/g_s2p  (no g_h roundtrip)
//   (b) fragment-packed tf32 store of h^T -> g_htf       (repack fused in)
// smem union: As/Bs during mainloop; 32x136 staging buffer in epilogue
// (stride 136: float4-aligned AND conflict-free for the gather reads).
// ---------------------------------------------------------------------------
#define STG 136

__global__ __launch_bounds__(256) void gemm_h_kernel(
    const float* __restrict__ A,    // inp [8192][512]
    const float* __restrict__ B,    // W1  [512][512]
    const float* __restrict__ bias, // b1  [512]
    const float* __restrict__ a1,
    const float* __restrict__ a2)
{
    __shared__ __align__(16) float smbuf[32 * STG];   // 17408 B
#define AS(k, r) smbuf[(k) * 132 + (r)]
#define BS(k, n) smbuf[1056 + (k) * 128 + (n)]

    const int tid = threadIdx.x;
    const int bx = blockIdx.x;      // f tile (0..3)
    const int by = blockIdx.y;      // j tile (0..63)
    const int tx = tid & 15;
    const int ty = tid >> 4;

    float acc[8][8];
#pragma unroll
    for (int i = 0; i < 8; i++)
#pragma unroll
        for (int j = 0; j < 8; j++) acc[i][j] = 0.f;

    const int a_r = tid >> 1;
    const int a_k = (tid & 1) * 4;
    const int b_k = tid >> 5;
    const int b_n = (tid & 31) * 4;

    const float* Aptr = A + (by * 128 + a_r) * GF + a_k;
    const float* Bptr = B + b_k * GF + bx * 128 + b_n;

    for (int k0 = 0; k0 < GF; k0 += 8) {
        float4 av = *(const float4*)(Aptr + k0);
        float4 bv = *(const float4*)(Bptr + k0 * GF);
        __syncthreads();
        AS(a_k + 0, a_r) = av.x;
        AS(a_k + 1, a_r) = av.y;
        AS(a_k + 2, a_r) = av.z;
        AS(a_k + 3, a_r) = av.w;
        *(float4*)&BS(b_k, b_n) = bv;
        __syncthreads();

#pragma unroll
        for (int kk = 0; kk < 8; kk++) {
            float af[8], bf[8];
#pragma unroll
            for (int i = 0; i < 8; i++) af[i] = AS(kk, ty * 8 + i);
#pragma unroll
            for (int j = 0; j < 8; j++) bf[j] = BS(kk, tx * 8 + j);
#pragma unroll
            for (int i = 0; i < 8; i++)
#pragma unroll
                for (int j = 0; j < 8; j++) acc[i][j] += af[i] * bf[j];
        }
    }

    const int col0 = bx * 128 + tx * 8;
    float4 bb0 = *(const float4*)(bias + col0);
    float4 bb1 = *(const float4*)(bias + col0 + 4);
#pragma unroll
    for (int i = 0; i < 8; i++) {
        acc[i][0] += bb0.x; acc[i][1] += bb0.y;
        acc[i][2] += bb0.z; acc[i][3] += bb0.w;
        acc[i][4] += bb1.x; acc[i][5] += bb1.y;
        acc[i][6] += bb1.z; acc[i][7] += bb1.w;
    }

    // ---- (a) s1/s2 partial dots over this CTA's 8 f-cols per thread
    {
        float4 va0 = *(const float4*)(a1 + col0);
        float4 va1 = *(const float4*)(a1 + col0 + 4);
        float4 vb0 = *(const float4*)(a2 + col0);
        float4 vb1 = *(const float4*)(a2 + col0 + 4);
        float s1p[8], s2p[8];
#pragma unroll
        for (int i = 0; i < 8; i++) {
            s1p[i] = acc[i][0] * va0.x + acc[i][1] * va0.y
                   + acc[i][2] * va0.z + acc[i][3] * va0.w
                   + acc[i][4] * va1.x + acc[i][5] * va1.y
                   + acc[i][6] * va1.z + acc[i][7] * va1.w;
            s2p[i] = acc[i][0] * vb0.x + acc[i][1] * vb0.y
                   + acc[i][2] * vb0.z + acc[i][3] * vb0.w
                   + acc[i][4] * vb1.x + acc[i][5] * vb1.y
                   + acc[i][6] * vb1.z + acc[i][7] * vb1.w;
        }
#pragma unroll
        for (int off = 8; off > 0; off >>= 1)
#pragma unroll
            for (int i = 0; i < 8; i++) {
                s1p[i] += __shfl_down_sync(0xffffffffu, s1p[i], off, 16);
                s2p[i] += __shfl_down_sync(0xffffffffu, s2p[i], off, 16);
            }
        if (tx == 0) {
            const int rbase = by * 128 + ty * 8;
#pragma unroll
            for (int i = 0; i < 8; i++) {
                g_s1p[bx][rbase + i] = s1p[i];
                g_s2p[bx][rbase + i] = s2p[i];
            }
        }
    }

    // ---- (b) fragment-packed tf32 h^T store, 4 chunks of 32 j-rows.
    // fragment layout (matches gat_attn4): float4 idx
    //   ((tglob*8 + bglob)*2 + kp)*256 + nt*32 + lane,
    //   element f = bglob*64 + nt*8 + gid, j = tglob*32 + kp*16 + slot*4 + tig
    const int tloc_of_ty = ty >> 2;
#pragma unroll
    for (int tl = 0; tl < 4; tl++) {
        __syncthreads();              // stage (aliases As/Bs) free to overwrite
        if (tloc_of_ty == tl) {
            const int rb = (ty & 3) * 8;
#pragma unroll
            for (int i = 0; i < 8; i++) {
                *(float4*)&smbuf[(rb + i) * STG + tx * 8] =
                    make_float4(acc[i][0], acc[i][1], acc[i][2], acc[i][3]);
                *(float4*)&smbuf[(rb + i) * STG + tx * 8 + 4] =
                    make_float4(acc[i][4], acc[i][5], acc[i][6], acc[i][7]);
            }
        }
        __syncthreads();

        const int tglob = by * 4 + tl;
#pragma unroll
        for (int p = 0; p < 4; p++) {
            const int o = tid + p * 256;         // float4 idx within chunk [0,1024)
            const int b_loc = o >> 9;
            const int kp    = (o >> 8) & 1;
            const int r     = o & 255;
            const int nt    = r >> 5;
            const int lane  = r & 31;
            const int gid   = lane >> 2;
            const int tig   = lane & 3;
            const int fcol  = b_loc * 64 + nt * 8 + gid;
            float4 v;
            v.x = smbuf[(kp * 16 + 0 * 4 + tig) * STG + fcol];
            v.y = smbuf[(kp * 16 + 1 * 4 + tig) * STG + fcol];
            v.z = smbuf[(kp * 16 + 2 * 4 + tig) * STG + fcol];
            v.w = smbuf[(kp * 16 + 3 * 4 + tig) * STG + fcol];
            unsigned u;
            asm("cvt.rna.tf32.f32 %0, %1;" : "=r"(u) : "f"(v.x)); v.x = __uint_as_float(u);
            asm("cvt.rna.tf32.f32 %0, %1;" : "=r"(u) : "f"(v.y)); v.y = __uint_as_float(u);
            asm("cvt.rna.tf32.f32 %0, %1;" : "=r"(u) : "f"(v.z)); v.z = __uint_as_float(u);
            asm("cvt.rna.tf32.f32 %0, %1;" : "=r"(u) : "f"(v.w)); v.w = __uint_as_float(u);
            const int bglob = bx * 2 + b_loc;
            ((float4*)g_htf)[(size_t)(((tglob * 8 + bglob) * 2 + kp)) * 256
                             + nt * 32 + lane] = v;
        }
    }
#undef AS
#undef BS
}

// ---------------------------------------------------------------------------
// Kernel 2: sum s1/s2 partials + factorized exp precompute
// ---------------------------------------------------------------------------
__global__ __launch_bounds__(256) void prep_kernel(const float* __restrict__ b2p)
{
    const int i = blockIdx.x * 256 + threadIdx.x;
    const float b2 = *b2p;
    const float s1 = g_s1p[0][i] + g_s1p[1][i] + g_s1p[2][i] + g_s1p[3][i];
    const float s2 = g_s2p[0][i] + g_s2p[1][i] + g_s2p[2][i] + g_s2p[3][i];
    const float x1 = s1 + b2;
    g_E1[i] = __expf(x1);
    g_F1[i] = __expf(0.2f * x1);
    g_E2[i] = __expf(s2);
    g_F2[i] = __expf(0.2f * s2);
}

// ---------------------------------------------------------------------------
// Kernel 3: fused attention — EXACT R11 winner (untouched).
// AM=32, AK=32, full F, 256 threads, 2 CTA/SM. B: direct LDG from
// fragment-packed g_htf. A: fragment-ready float4 via 4KB smem PF.
// ---------------------------------------------------------------------------
#define AM 32
#define AK 32
#define NTT (GN / AK)                    // 256

__device__ __forceinline__ void mma8(float* c, float4 a, float b0, float b1)
{
    asm volatile(
        "mma.sync.aligned.m16n8k8.row.col.f32.tf32.tf32.f32 "
        "{%0,%1,%2,%3}, {%4,%5,%6,%7}, {%8,%9}, {%0,%1,%2,%3};\n"
        : "+f"(c[0]), "+f"(c[1]), "+f"(c[2]), "+f"(c[3])
        : "r"(__float_as_uint(a.x)), "r"(__float_as_uint(a.y)),
          "r"(__float_as_uint(a.z)), "r"(__float_as_uint(a.w)),
          "r"(__float_as_uint(b0)), "r"(__float_as_uint(b1)));
}

__device__ __forceinline__ float tf32r(float x)
{
    unsigned u;
    asm("cvt.rna.tf32.f32 %0, %1;" : "=r"(u) : "f"(x));
    return __uint_as_float(u);
}

__global__ __launch_bounds__(256, 2) void gat_attn4(
    const int* __restrict__ adj, float* __restrict__ out)
{
    __shared__ float4 PF[256];           // 8 A-frags x 32 lanes
    __shared__ float  ls[AM];

    const int tid  = threadIdx.x;
    const int w    = tid >> 5;           // warp 0..7 == producer frag id
    const int lane = tid & 31;
    const int gid  = lane >> 2;
    const int tig  = lane & 3;
    const int i0   = blockIdx.x * AM;

    if (tid < AM) ls[tid] = 0.f;

    // producer identity: frag f = w = ks*2+mt
    const int pks = w >> 1;
    const int pmt = w & 1;
    const int r0 = pmt * 16 + gid, r1 = r0 + 8;
    const int c0 = pks * 8 + tig,  c1 = c0 + 4;

    const float e1a = g_E1[i0 + r0], f1a = g_F1[i0 + r0];
    const float e1b = g_E1[i0 + r1], f1b = g_F1[i0 + r1];
    const int* arow0 = adj + (size_t)(i0 + r0) * GN;
    const int* arow1 = adj + (size_t)(i0 + r1) * GN;

    float lacc0 = 0.f, lacc1 = 0.f;
    float acc[2][8][4];
#pragma unroll
    for (int mt = 0; mt < 2; mt++)
#pragma unroll
        for (int nt = 0; nt < 8; nt++)
#pragma unroll
            for (int q = 0; q < 4; q++) acc[mt][nt][q] = 0.f;

    int a00, a01, a10, a11;
    float E2a, E2b, F2a, F2b;

#define PREF(J) do {                                                       \
    a00 = __ldg(arow0 + (J) + c0); a01 = __ldg(arow0 + (J) + c1);          \
    a10 = __ldg(arow1 + (J) + c0); a11 = __ldg(arow1 + (J) + c1);          \
    E2a = __ldg(&g_E2[(J) + c0]);  E2b = __ldg(&g_E2[(J) + c1]);           \
    F2a = __ldg(&g_F2[(J) + c0]);  F2b = __ldg(&g_F2[(J) + c1]);           \
} while (0)

    PREF(0);

    // B base: warp w reads float4 idx ((t*8+w)*2+kp)*256 + nt*32 + lane
    const float4* bwarp = (const float4*)g_htf + (size_t)w * 512 + lane;

    for (int t = 0; t < NTT; t++) {
        // ---- produce P fragments (factorized exp, zero MUFU)
        {
            float u00 = e1a * E2a, v00 = f1a * F2a;
            float u01 = e1a * E2b, v01 = f1a * F2b;
            float u10 = e1b * E2a, v10 = f1b * F2a;
            float u11 = e1b * E2b, v11 = f1b * F2b;
            float p00 = (a00 > 0) ? (u00 > 1.f ? u00 : v00) : 0.f;
            float p01 = (a01 > 0) ? (u01 > 1.f ? u01 : v01) : 0.f;
            float p10 = (a10 > 0) ? (u10 > 1.f ? u10 : v10) : 0.f;
            float p11 = (a11 > 0) ? (u11 > 1.f ? u11 : v11) : 0.f;
            p00 = tf32r(p00); p01 = tf32r(p01);
            p10 = tf32r(p10); p11 = tf32r(p11);
            lacc0 += p00 + p01; lacc1 += p10 + p11;
            PF[tid] = make_float4(p00, p10, p01, p11);
        }
        __syncthreads();                     // PF ready

        if (t + 1 < NTT) PREF((t + 1) * AK); // hide adj/EF latency under MMA

        const float4* bt = bwarp + (size_t)t * 4096;
#pragma unroll
        for (int kp = 0; kp < 2; kp++) {
            float4 bq[8];
#pragma unroll
            for (int nt = 0; nt < 8; nt++)
                bq[nt] = __ldg(bt + (size_t)kp * 256 + nt * 32);

            // A frags for ks = 2kp, 2kp+1 (frag f = ks*2+mt)
            const float4 afA0 = PF[(4 * kp + 0) * 32 + lane];
            const float4 afA1 = PF[(4 * kp + 1) * 32 + lane];
            const float4 afB0 = PF[(4 * kp + 2) * 32 + lane];
            const float4 afB1 = PF[(4 * kp + 3) * 32 + lane];

#pragma unroll
            for (int nt = 0; nt < 8; nt++) {
                mma8(acc[0][nt], afA0, bq[nt].x, bq[nt].y);
                mma8(acc[1][nt], afA1, bq[nt].x, bq[nt].y);
                mma8(acc[0][nt], afB0, bq[nt].z, bq[nt].w);
                mma8(acc[1][nt], afB1, bq[nt].z, bq[nt].w);
            }
        }
        __syncthreads();                     // PF consumed (WAR for t+1)
    }

    // ---- row sums: 16 threads contribute per row
    atomicAdd(&ls[r0], lacc0);
    atomicAdd(&ls[r1], lacc1);
    __syncthreads();

    // ---- epilogue: normalize + elu + store
#pragma unroll
    for (int mt = 0; mt < 2; mt++) {
        const int rA = mt * 16 + gid;
        const int rB = rA + 8;
        const float invA = 1.0f / ls[rA];
        const float invB = 1.0f / ls[rB];
#pragma unroll
        for (int nt = 0; nt < 8; nt++) {
            const int col = w * 64 + nt * 8 + tig * 2;
            float o0 = acc[mt][nt][0] * invA;
            float o1 = acc[mt][nt][1] * invA;
            float o2 = acc[mt][nt][2] * invB;
            float o3 = acc[mt][nt][3] * invB;
            o0 = o0 > 0.f ? o0 : (__expf(o0) - 1.f);
            o1 = o1 > 0.f ? o1 : (__expf(o1) - 1.f);
            o2 = o2 > 0.f ? o2 : (__expf(o2) - 1.f);
            o3 = o3 > 0.f ? o3 : (__expf(o3) - 1.f);
            *(float2*)&out[(size_t)(i0 + rA) * GF + col] = make_float2(o0, o1);
            *(float2*)&out[(size_t)(i0 + rB) * GF + col] = make_float2(o2, o3);
        }
    }
}

// ---------------------------------------------------------------------------
extern "C" void kernel_launch(void* const* d_in, const int* in_sizes, int n_in,
                              void* d_out, int out_size)
{
    const float* inp = (const float*)d_in[0];
    const int*   adj = (const int*)d_in[1];
    const float* W1  = (const float*)d_in[2];
    const float* b1  = (const float*)d_in[3];
    const float* a1  = (const float*)d_in[4];
    const float* a2  = (const float*)d_in[5];
    const float* b2  = (const float*)d_in[6];
    float* out = (float*)d_out;

    (void)in_sizes; (void)n_in; (void)out_size;

    gemm_h_kernel<<<dim3(GF / 128, GN / 128), 256>>>(inp, W1, b1, a1, a2);
    prep_kernel<<<GN / 256, 256>>>(b2);
    gat_attn4<<<GN / AM, 256>>>(adj, out);
}

// round 17
// speedup vs baseline: 1.5540x; 1.1051x over previous
#include <cuda_runtime.h>
#include <math.h>
#include <stdint.h>

#define GN 8192
#define GF 512

// ---------------- device scratch (allocation-free) ----------------
__device__ __align__(16) float g_htf[GF * GN];  // h^T tf32, FRAGMENT-PACKED
__device__ __align__(16) float g_w1f[GF * GF];  // W1 tf32, FRAGMENT-PACKED
__device__ float g_s1[GN], g_s2[GN];
__device__ float g_E1[GN], g_F1[GN], g_E2[GN], g_F2[GN];

#define STG 136   // staging stride: float4-aligned, conflict-free gather

__device__ __forceinline__ void mma8(float* c, float4 a, float b0, float b1)
{
    asm volatile(
        "mma.sync.aligned.m16n8k8.row.col.f32.tf32.tf32.f32 "
        "{%0,%1,%2,%3}, {%4,%5,%6,%7}, {%8,%9}, {%0,%1,%2,%3};\n"
        : "+f"(c[0]), "+f"(c[1]), "+f"(c[2]), "+f"(c[3])
        : "r"(__float_as_uint(a.x)), "r"(__float_as_uint(a.y)),
          "r"(__float_as_uint(a.z)), "r"(__float_as_uint(a.w)),
          "r"(__float_as_uint(b0)), "r"(__float_as_uint(b1)));
}

__device__ __forceinline__ float tf32r(float x)
{
    unsigned u;
    asm("cvt.rna.tf32.f32 %0, %1;" : "=r"(u) : "f"(x));
    return __uint_as_float(u);
}

// ---------------------------------------------------------------------------
// Kernel 0: repack W1 -> g_w1f (tf32, mma-fragment order).
// Block (w=0..7, kt=0..15): f in [w*64,+64), k in [kt*32,+32).
// float4 idx: ((kt*8+w)*2+kp)*256 + nt*32 + lane;
// element f = w*64+nt*8+gid, k = kt*32+kp*16+slot*4+tig.  Value = W1[k][f].
// ---------------------------------------------------------------------------
__global__ __launch_bounds__(256) void repack_w1_kernel(const float* __restrict__ W1)
{
    __shared__ float sm[32][68];
    const int tid = threadIdx.x;
    const int w  = blockIdx.x;
    const int kt = blockIdx.y;

#pragma unroll
    for (int rep = 0; rep < 2; rep++) {
        const int idx = tid + rep * 256;
        const int k = idx >> 4, fq = idx & 15;
        float4 v = *(const float4*)&W1[(size_t)(kt * 32 + k) * GF + w * 64 + fq * 4];
        v.x = tf32r(v.x); v.y = tf32r(v.y); v.z = tf32r(v.z); v.w = tf32r(v.w);
        *(float4*)&sm[k][fq * 4] = v;
    }
    __syncthreads();

    float4* dst = (float4*)g_w1f + (size_t)(kt * 8 + w) * 512;
#pragma unroll
    for (int rep = 0; rep < 2; rep++) {
        const int o = tid + rep * 256;
        const int kp = o >> 8, r = o & 255;
        const int nt = r >> 5, lane = r & 31;
        const int gid = lane >> 2, tig = lane & 3;
        const int fl = nt * 8 + gid;
        float4 v;
        v.x = sm[kp * 16 + 0 * 4 + tig][fl];
        v.y = sm[kp * 16 + 1 * 4 + tig][fl];
        v.z = sm[kp * 16 + 2 * 4 + tig][fl];
        v.w = sm[kp * 16 + 3 * 4 + tig][fl];
        dst[o] = v;
    }
}

// ---------------------------------------------------------------------------
// Kernel 1: h = inp @ W1 + b1 via tf32 mma.sync — SAME template as the proven
// attention kernel. CTA = 32 j-rows x full 512 f, 256 threads, 16 K-tiles.
// A-fragments: inp values tf32-rounded into PF; B: direct LDG from g_w1f.
// Fused epilogue: bias, s1/s2 full row dots -> g_s1/g_s2, fragment-packed
// tf32 h^T -> g_htf (4 staging chunks of 128 f, stride-136 conflict-free).
// ---------------------------------------------------------------------------
#define NTK (GF / 32)                    // 16

__global__ __launch_bounds__(256, 2) void gemm_tc_kernel(
    const float* __restrict__ inp,
    const float* __restrict__ bias,
    const float* __restrict__ a1,
    const float* __restrict__ a2)
{
    __shared__ float4 PF[256];
    __shared__ __align__(16) float smstage[32 * STG];
    __shared__ float s1s[32], s2s[32];

    const int tid  = threadIdx.x;
    const int w    = tid >> 5;
    const int lane = tid & 31;
    const int gid  = lane >> 2;
    const int tig  = lane & 3;
    const int j0   = blockIdx.x * 32;

    if (tid < 32) { s1s[tid] = 0.f; s2s[tid] = 0.f; }

    // producer identity: frag f = w = pks*2+pmt
    const int pks = w >> 1;
    const int pmt = w & 1;
    const int r0 = pmt * 16 + gid, r1 = r0 + 8;
    const int c0 = pks * 8 + tig,  c1 = c0 + 4;

    const float* arow0 = inp + (size_t)(j0 + r0) * GF;
    const float* arow1 = inp + (size_t)(j0 + r1) * GF;

    float acc[2][8][4];
#pragma unroll
    for (int mt = 0; mt < 2; mt++)
#pragma unroll
        for (int nt = 0; nt < 8; nt++)
#pragma unroll
            for (int q = 0; q < 4; q++) acc[mt][nt][q] = 0.f;

    float x00, x01, x10, x11;

#define GPREF(KT) do {                                                     \
    x00 = __ldg(arow0 + (KT) * 32 + c0);                                   \
    x01 = __ldg(arow0 + (KT) * 32 + c1);                                   \
    x10 = __ldg(arow1 + (KT) * 32 + c0);                                   \
    x11 = __ldg(arow1 + (KT) * 32 + c1);                                   \
} while (0)

    GPREF(0);

    // B base: warp w reads float4 idx ((kt*8+w)*2+kp)*256 + nt*32 + lane
    const float4* bwarp = (const float4*)g_w1f + (size_t)w * 512 + lane;

    for (int kt = 0; kt < NTK; kt++) {
        PF[tid] = make_float4(tf32r(x00), tf32r(x10), tf32r(x01), tf32r(x11));
        __syncthreads();                     // PF ready

        if (kt + 1 < NTK) GPREF(kt + 1);

        const float4* bt = bwarp + (size_t)kt * 4096;
#pragma unroll
        for (int kp = 0; kp < 2; kp++) {
            float4 bq[8];
#pragma unroll
            for (int nt = 0; nt < 8; nt++)
                bq[nt] = __ldg(bt + (size_t)kp * 256 + nt * 32);

            const float4 afA0 = PF[(4 * kp + 0) * 32 + lane];
            const float4 afA1 = PF[(4 * kp + 1) * 32 + lane];
            const float4 afB0 = PF[(4 * kp + 2) * 32 + lane];
            const float4 afB1 = PF[(4 * kp + 3) * 32 + lane];

#pragma unroll
            for (int nt = 0; nt < 8; nt++) {
                mma8(acc[0][nt], afA0, bq[nt].x, bq[nt].y);
                mma8(acc[1][nt], afA1, bq[nt].x, bq[nt].y);
                mma8(acc[0][nt], afB0, bq[nt].z, bq[nt].w);
                mma8(acc[1][nt], afB1, bq[nt].z, bq[nt].w);
            }
        }
        __syncthreads();                     // PF consumed
    }

    // ---- bias add + s1/s2 row-dot partials
    float p1[2][2] = {{0.f, 0.f}, {0.f, 0.f}};
    float p2[2][2] = {{0.f, 0.f}, {0.f, 0.f}};
#pragma unroll
    for (int nt = 0; nt < 8; nt++) {
        const int col = w * 64 + nt * 8 + tig * 2;
        const float2 bb = *(const float2*)&bias[col];
        const float2 va = *(const float2*)&a1[col];
        const float2 vb = *(const float2*)&a2[col];
#pragma unroll
        for (int mt = 0; mt < 2; mt++) {
            acc[mt][nt][0] += bb.x; acc[mt][nt][1] += bb.y;
            acc[mt][nt][2] += bb.x; acc[mt][nt][3] += bb.y;
            p1[mt][0] += acc[mt][nt][0] * va.x + acc[mt][nt][1] * va.y;
            p1[mt][1] += acc[mt][nt][2] * va.x + acc[mt][nt][3] * va.y;
            p2[mt][0] += acc[mt][nt][0] * vb.x + acc[mt][nt][1] * vb.y;
            p2[mt][1] += acc[mt][nt][2] * vb.x + acc[mt][nt][3] * vb.y;
        }
    }
#pragma unroll
    for (int mt = 0; mt < 2; mt++) {
        atomicAdd(&s1s[mt * 16 + gid],     p1[mt][0]);
        atomicAdd(&s1s[mt * 16 + gid + 8], p1[mt][1]);
        atomicAdd(&s2s[mt * 16 + gid],     p2[mt][0]);
        atomicAdd(&s2s[mt * 16 + gid + 8], p2[mt][1]);
    }
    __syncthreads();
    if (tid < 32) {
        g_s1[j0 + tid] = s1s[tid];
        g_s2[j0 + tid] = s2s[tid];
    }

    // ---- fragment-packed tf32 h^T store, 4 chunks of 128 f-cols
#pragma unroll
    for (int c = 0; c < 4; c++) {
        __syncthreads();
        if ((w >> 1) == c) {
            const int flb = (w & 1) * 64;
#pragma unroll
            for (int mt = 0; mt < 2; mt++)
#pragma unroll
                for (int nt = 0; nt < 8; nt++) {
                    const int fl = flb + nt * 8 + tig * 2;
                    smstage[(mt * 16 + gid) * STG + fl]         = acc[mt][nt][0];
                    smstage[(mt * 16 + gid) * STG + fl + 1]     = acc[mt][nt][1];
                    smstage[(mt * 16 + gid + 8) * STG + fl]     = acc[mt][nt][2];
                    smstage[(mt * 16 + gid + 8) * STG + fl + 1] = acc[mt][nt][3];
                }
        }
        __syncthreads();

#pragma unroll
        for (int p = 0; p < 4; p++) {
            const int o = tid + p * 256;
            const int b_loc = o >> 9;
            const int kp    = (o >> 8) & 1;
            const int r     = o & 255;
            const int nt    = r >> 5;
            const int ln    = r & 31;
            const int ggid  = ln >> 2;
            const int gtig  = ln & 3;
            const int fcol  = b_loc * 64 + nt * 8 + ggid;
            float4 v;
            v.x = smstage[(kp * 16 + 0 * 4 + gtig) * STG + fcol];
            v.y = smstage[(kp * 16 + 1 * 4 + gtig) * STG + fcol];
            v.z = smstage[(kp * 16 + 2 * 4 + gtig) * STG + fcol];
            v.w = smstage[(kp * 16 + 3 * 4 + gtig) * STG + fcol];
            v.x = tf32r(v.x); v.y = tf32r(v.y); v.z = tf32r(v.z); v.w = tf32r(v.w);
            const int bglob = c * 2 + b_loc;
            ((float4*)g_htf)[(size_t)((blockIdx.x * 8 + bglob) * 2 + kp) * 256
                             + nt * 32 + ln] = v;
        }
    }
}

// ---------------------------------------------------------------------------
// Kernel 2: factorized exp precompute
// ---------------------------------------------------------------------------
__global__ __launch_bounds__(256) void prep_kernel(const float* __restrict__ b2p)
{
    const int i = blockIdx.x * 256 + threadIdx.x;
    const float b2 = *b2p;
    const float x1 = g_s1[i] + b2;
    const float x2 = g_s2[i];
    g_E1[i] = __expf(x1);
    g_F1[i] = __expf(0.2f * x1);
    g_E2[i] = __expf(x2);
    g_F2[i] = __expf(0.2f * x2);
}

// ---------------------------------------------------------------------------
// Kernel 3: fused attention — EXACT R11/R16 winner (untouched).
// ---------------------------------------------------------------------------
#define AM 32
#define AK 32
#define NTT (GN / AK)                    // 256

__global__ __launch_bounds__(256, 2) void gat_attn4(
    const int* __restrict__ adj, float* __restrict__ out)
{
    __shared__ float4 PF[256];           // 8 A-frags x 32 lanes
    __shared__ float  ls[AM];

    const int tid  = threadIdx.x;
    const int w    = tid >> 5;           // warp 0..7 == producer frag id
    const int lane = tid & 31;
    const int gid  = lane >> 2;
    const int tig  = lane & 3;
    const int i0   = blockIdx.x * AM;

    if (tid < AM) ls[tid] = 0.f;

    // producer identity: frag f = w = ks*2+mt
    const int pks = w >> 1;
    const int pmt = w & 1;
    const int r0 = pmt * 16 + gid, r1 = r0 + 8;
    const int c0 = pks * 8 + tig,  c1 = c0 + 4;

    const float e1a = g_E1[i0 + r0], f1a = g_F1[i0 + r0];
    const float e1b = g_E1[i0 + r1], f1b = g_F1[i0 + r1];
    const int* arow0 = adj + (size_t)(i0 + r0) * GN;
    const int* arow1 = adj + (size_t)(i0 + r1) * GN;

    float lacc0 = 0.f, lacc1 = 0.f;
    float acc[2][8][4];
#pragma unroll
    for (int mt = 0; mt < 2; mt++)
#pragma unroll
        for (int nt = 0; nt < 8; nt++)
#pragma unroll
            for (int q = 0; q < 4; q++) acc[mt][nt][q] = 0.f;

    int a00, a01, a10, a11;
    float E2a, E2b, F2a, F2b;

#define PREF(J) do {                                                       \
    a00 = __ldg(arow0 + (J) + c0); a01 = __ldg(arow0 + (J) + c1);          \
    a10 = __ldg(arow1 + (J) + c0); a11 = __ldg(arow1 + (J) + c1);          \
    E2a = __ldg(&g_E2[(J) + c0]);  E2b = __ldg(&g_E2[(J) + c1]);           \
    F2a = __ldg(&g_F2[(J) + c0]);  F2b = __ldg(&g_F2[(J) + c1]);           \
} while (0)

    PREF(0);

    // B base: warp w reads float4 idx ((t*8+w)*2+kp)*256 + nt*32 + lane
    const float4* bwarp = (const float4*)g_htf + (size_t)w * 512 + lane;

    for (int t = 0; t < NTT; t++) {
        // ---- produce P fragments (factorized exp, zero MUFU)
        {
            float u00 = e1a * E2a, v00 = f1a * F2a;
            float u01 = e1a * E2b, v01 = f1a * F2b;
            float u10 = e1b * E2a, v10 = f1b * F2a;
            float u11 = e1b * E2b, v11 = f1b * F2b;
            float p00 = (a00 > 0) ? (u00 > 1.f ? u00 : v00) : 0.f;
            float p01 = (a01 > 0) ? (u01 > 1.f ? u01 : v01) : 0.f;
            float p10 = (a10 > 0) ? (u10 > 1.f ? u10 : v10) : 0.f;
            float p11 = (a11 > 0) ? (u11 > 1.f ? u11 : v11) : 0.f;
            p00 = tf32r(p00); p01 = tf32r(p01);
            p10 = tf32r(p10); p11 = tf32r(p11);
            lacc0 += p00 + p01; lacc1 += p10 + p11;
            PF[tid] = make_float4(p00, p10, p01, p11);
        }
        __syncthreads();                     // PF ready

        if (t + 1 < NTT) PREF((t + 1) * AK); // hide adj/EF latency under MMA

        const float4* bt = bwarp + (size_t)t * 4096;
#pragma unroll
        for (int kp = 0; kp < 2; kp++) {
            float4 bq[8];
#pragma unroll
            for (int nt = 0; nt < 8; nt++)
                bq[nt] = __ldg(bt + (size_t)kp * 256 + nt * 32);

            const float4 afA0 = PF[(4 * kp + 0) * 32 + lane];
            const float4 afA1 = PF[(4 * kp + 1) * 32 + lane];
            const float4 afB0 = PF[(4 * kp + 2) * 32 + lane];
            const float4 afB1 = PF[(4 * kp + 3) * 32 + lane];

#pragma unroll
            for (int nt = 0; nt < 8; nt++) {
                mma8(acc[0][nt], afA0, bq[nt].x, bq[nt].y);
                mma8(acc[1][nt], afA1, bq[nt].x, bq[nt].y);
                mma8(acc[0][nt], afB0, bq[nt].z, bq[nt].w);
                mma8(acc[1][nt], afB1, bq[nt].z, bq[nt].w);
            }
        }
        __syncthreads();                     // PF consumed (WAR for t+1)
    }

    // ---- row sums: 16 threads contribute per row
    atomicAdd(&ls[r0], lacc0);
    atomicAdd(&ls[r1], lacc1);
    __syncthreads();

    // ---- epilogue: normalize + elu + store
#pragma unroll
    for (int mt = 0; mt < 2; mt++) {
        const int rA = mt * 16 + gid;
        const int rB = rA + 8;
        const float invA = 1.0f / ls[rA];
        const float invB = 1.0f / ls[rB];
#pragma unroll
        for (int nt = 0; nt < 8; nt++) {
            const int col = w * 64 + nt * 8 + tig * 2;
            float o0 = acc[mt][nt][0] * invA;
            float o1 = acc[mt][nt][1] * invA;
            float o2 = acc[mt][nt][2] * invB;
            float o3 = acc[mt][nt][3] * invB;
            o0 = o0 > 0.f ? o0 : (__expf(o0) - 1.f);
            o1 = o1 > 0.f ? o1 : (__expf(o1) - 1.f);
            o2 = o2 > 0.f ? o2 : (__expf(o2) - 1.f);
            o3 = o3 > 0.f ? o3 : (__expf(o3) - 1.f);
            *(float2*)&out[(size_t)(i0 + rA) * GF + col] = make_float2(o0, o1);
            *(float2*)&out[(size_t)(i0 + rB) * GF + col] = make_float2(o2, o3);
        }
    }
}

// ---------------------------------------------------------------------------
extern "C" void kernel_launch(void* const* d_in, const int* in_sizes, int n_in,
                              void* d_out, int out_size)
{
    const float* inp = (const float*)d_in[0];
    const int*   adj = (const int*)d_in[1];
    const float* W1  = (const float*)d_in[2];
    const float* b1  = (const float*)d_in[3];
    const float* a1  = (const float*)d_in[4];
    const float* a2  = (const float*)d_in[5];
    const float* b2  = (const float*)d_in[6];
    float* out = (float*)d_out;

    (void)in_sizes; (void)n_in; (void)out_size;

    repack_w1_kernel<<<dim3(8, 16), 256>>>(W1);
    gemm_tc_kernel<<<GN / 32, 256>>>(inp, b1, a1, a2);
    prep_kernel<<<GN / 256, 256>>>(b2);
    gat_attn4<<<GN / AM, 256>>>(adj, out);
}